// round 6
// baseline (speedup 1.0000x reference)
#include <cuda_runtime.h>
#include <cstdint>

typedef unsigned long long u64;

#define L2E 1.4426950408889634f

// ---------------- folded-parameter block layout (floats) ----------------
#define OFF_PDS 0     // 10 x 8 pairs: prototypes duplicated, scaled by 2*L2E (160)
#define OFF_PPL 160   // 10 pairs: -L2E * |p|^2 (20)
#define OFF_AD  180   // 2 x 10 x 20: attn matrix as dup pairs [l][i][j] (400)
#define OFF_ABD 580   // 2 x 20: folded attn bias dup pairs (40)
#define OFF_W1  620   // 2 x 10 x 64: diag(ln2_g) @ W1 (1280)
#define OFF_B1  1900  // 2 x 64: b1 + ln2_b @ W1 (128)
#define OFF_W2  2028  // 2 x 64 x 12 row-padded (1536)
#define OFF_B2  3564  // 2 x 12 (24)
#define OFF_WCN 3588  // 10 pairs: -L2E * Wc (20)
#define OFF_BCN 3608  // 1: -L2E * bc
#define NPAR    3616

__device__ float g_par[NPAR];

// ---------------- packed f32x2 helpers ----------------
__device__ __forceinline__ u64 pk2(float lo, float hi) {
    u64 r; asm("mov.b64 %0,{%1,%2};" : "=l"(r) : "f"(lo), "f"(hi)); return r;
}
__device__ __forceinline__ void upk2(u64 v, float& lo, float& hi) {
    asm("mov.b64 {%0,%1},%2;" : "=f"(lo), "=f"(hi) : "l"(v));
}
__device__ __forceinline__ u64 fma2_(u64 a, u64 b, u64 c) {
    u64 d; asm("fma.rn.f32x2 %0,%1,%2,%3;" : "=l"(d) : "l"(a), "l"(b), "l"(c)); return d;
}
__device__ __forceinline__ u64 mul2_(u64 a, u64 b) {
    u64 d; asm("mul.rn.f32x2 %0,%1,%2;" : "=l"(d) : "l"(a), "l"(b)); return d;
}
__device__ __forceinline__ u64 add2_(u64 a, u64 b) {
    u64 d; asm("add.rn.f32x2 %0,%1,%2;" : "=l"(d) : "l"(a), "l"(b)); return d;
}
__device__ __forceinline__ float tanh_a(float u) {
    float th; asm("tanh.approx.f32 %0,%1;" : "=f"(th) : "f"(u)); return th;
}
__device__ __forceinline__ float ex2_a(float u) {
    float r; asm("ex2.approx.f32 %0,%1;" : "=f"(r) : "f"(u)); return r;
}

// Packed tanh-gelu: gelu(t) = ht + ht*tanh(u), ht=0.5t, u=t*(K0+K1*t^2)
__device__ __forceinline__ u64 gelu2(u64 t) {
    const u64 K1   = pk2(0.03567740814f, 0.03567740814f);
    const u64 K0   = pk2(0.7978845608f,  0.7978845608f);
    const u64 HALF = pk2(0.5f, 0.5f);
    u64 tt = mul2_(t, t);
    u64 in = fma2_(tt, K1, K0);
    u64 u  = mul2_(t, in);
    float u0, u1; upk2(u, u0, u1);
    u64 th = pk2(tanh_a(u0), tanh_a(u1));
    u64 ht = mul2_(t, HALF);
    return fma2_(ht, th, ht);
}

// Sample-packed LayerNorm over 10 features.
__device__ __forceinline__ void ln10p(const u64* sP, u64* nP) {
    const u64 TENTH = pk2(0.1f, 0.1f);
    const u64 NEG1  = pk2(-1.0f, -1.0f);
    u64 m01 = add2_(sP[0], sP[1]);
    u64 m23 = add2_(sP[2], sP[3]);
    u64 m45 = add2_(sP[4], sP[5]);
    u64 m67 = add2_(sP[6], sP[7]);
    u64 m89 = add2_(sP[8], sP[9]);
    u64 mu = add2_(add2_(add2_(m01, m23), add2_(m45, m67)), m89);
    mu = mul2_(mu, TENTH);
    u64 nmu = mul2_(mu, NEG1);
    u64 d[10];
#pragma unroll
    for (int j = 0; j < 10; j++) d[j] = add2_(sP[j], nmu);
    u64 v = mul2_(d[0], d[0]);
#pragma unroll
    for (int j = 1; j < 10; j++) v = fma2_(d[j], d[j], v);
    v = mul2_(v, TENTH);
    float vA, vB; upk2(v, vA, vB);
    u64 rp = pk2(rsqrtf(vA + 1e-5f), rsqrtf(vB + 1e-5f));
#pragma unroll
    for (int j = 0; j < 10; j++) nP[j] = mul2_(d[j], rp);
}

// ---------------- one-time weight folding ----------------
// seq-len==1 => softmax(1x1)==1 => attention output == V:
//   seq += LN1(seq) @ (diag(g1) Wv Wo) + (b1ln @ (Wv Wo) + bv @ Wo + bo)
__global__ void fold_kernel(
    const float* __restrict__ proto,
    const float* __restrict__ Wv, const float* __restrict__ bv,
    const float* __restrict__ Wo, const float* __restrict__ bo,
    const float* __restrict__ g1, const float* __restrict__ b1ln,
    const float* __restrict__ g2, const float* __restrict__ b2ln,
    const float* __restrict__ W1, const float* __restrict__ b1,
    const float* __restrict__ W2, const float* __restrict__ b2,
    const float* __restrict__ Wc, const float* __restrict__ bc)
{
    int t = threadIdx.x;
    for (int i = t; i < NPAR; i += 256) g_par[i] = 0.0f;
    __syncthreads();

    for (int i = t; i < 80; i += 256) {
        float v = 2.0f * L2E * proto[i];
        g_par[OFF_PDS + 2 * i] = v;
        g_par[OFF_PDS + 2 * i + 1] = v;
    }
    if (t < 10) {
        float s = 0.0f;
        for (int d = 0; d < 8; d++) s += proto[t * 8 + d] * proto[t * 8 + d];
        g_par[OFF_PPL + 2 * t] = -L2E * s;
        g_par[OFF_PPL + 2 * t + 1] = -L2E * s;
    }
#pragma unroll
    for (int l = 0; l < 2; l++) {
        if (t < 100) {
            int i = t / 10, j = t % 10;
            float m = 0.0f;
            for (int k = 0; k < 10; k++) m += Wv[l * 100 + i * 10 + k] * Wo[l * 100 + k * 10 + j];
            float v = g1[l * 10 + i] * m;
            int base = OFF_AD + l * 200 + i * 20 + 2 * j;
            g_par[base] = v; g_par[base + 1] = v;
        }
        if (t < 10) {  // folded attention bias, j = t
            float s = bo[l * 10 + t];
            for (int k = 0; k < 10; k++) s += bv[l * 10 + k] * Wo[l * 100 + k * 10 + t];
            for (int i = 0; i < 10; i++) {
                float m = 0.0f;
                for (int k = 0; k < 10; k++) m += Wv[l * 100 + i * 10 + k] * Wo[l * 100 + k * 10 + t];
                s += b1ln[l * 10 + i] * m;
            }
            int base = OFF_ABD + l * 20 + 2 * t;
            g_par[base] = s; g_par[base + 1] = s;
        }
        for (int e = t; e < 640; e += 256) {
            int i = e / 64;
            g_par[OFF_W1 + l * 640 + e] = g2[l * 10 + i] * W1[l * 640 + e];
        }
        if (t < 64) {
            float s = b1[l * 64 + t];
            for (int i = 0; i < 10; i++) s += b2ln[l * 10 + i] * W1[l * 640 + i * 64 + t];
            g_par[OFF_B1 + l * 64 + t] = s;
        }
        for (int e = t; e < 640; e += 256) {
            int f = e / 10, j = e % 10;
            g_par[OFF_W2 + l * 768 + f * 12 + j] = W2[l * 640 + e];
        }
        if (t < 10) g_par[OFF_B2 + l * 12 + t] = b2[l * 10 + t];
    }
    if (t < 10) {
        float w = -L2E * Wc[t];
        g_par[OFF_WCN + 2 * t] = w;
        g_par[OFF_WCN + 2 * t + 1] = w;
    }
    if (t == 0) g_par[OFF_BCN] = -L2E * bc[0];
}

// ---------------- main kernel: 2 samples per thread, sample-packed state ----------------
__global__ void __launch_bounds__(256) fwd_kernel(
    const float* __restrict__ x, float* __restrict__ out, int B)
{
    __shared__ __align__(16) float sm[NPAR];
    for (int i = threadIdx.x; i < NPAR; i += 256) sm[i] = g_par[i];
    __syncthreads();

    int pid = blockIdx.x * 256 + threadIdx.x;   // pair id
    int i0 = pid * 2;
    if (i0 >= B) return;
    bool haveB = (i0 + 1 < B);

    const float4* xp = reinterpret_cast<const float4*>(x) + (u64)i0 * 2;
    float4 xa0 = xp[0], xb0 = xp[1];
    float4 xa1 = haveB ? xp[2] : xa0;
    float4 xb1 = haveB ? xp[3] : xb0;

    const u64 NL2E = pk2(-L2E, -L2E);

    // sample-packed input components
    u64 X[8];
    X[0] = pk2(xa0.x, xa1.x); X[1] = pk2(xa0.y, xa1.y);
    X[2] = pk2(xa0.z, xa1.z); X[3] = pk2(xa0.w, xa1.w);
    X[4] = pk2(xb0.x, xb1.x); X[5] = pk2(xb0.y, xb1.y);
    X[6] = pk2(xb0.z, xb1.z); X[7] = pk2(xb0.w, xb1.w);

    u64 x2p = mul2_(X[0], X[0]);
#pragma unroll
    for (int c = 1; c < 8; c++) x2p = fma2_(X[c], X[c], x2p);
    u64 nx2L = mul2_(x2p, NL2E);   // -L2E * |x|^2 (packed)

    // RBF: exp2( L2E*(2 x.p - |x|^2 - |p|^2) ); all scales pre-folded
    u64 sP[10];
#pragma unroll
    for (int j = 0; j < 10; j++) {
        const u64* pd = reinterpret_cast<const u64*>(&sm[OFF_PDS + j * 16]);
        u64 dp = mul2_(X[0], pd[0]);
#pragma unroll
        for (int c = 1; c < 8; c++) dp = fma2_(X[c], pd[c], dp);
        u64 pre = *reinterpret_cast<const u64*>(&sm[OFF_PPL + 2 * j]);
        u64 arg = add2_(dp, add2_(nx2L, pre));
        float a0, a1; upk2(arg, a0, a1);
        sP[j] = pk2(ex2_a(a0), ex2_a(a1));
    }

    u64 nP[10];

#pragma unroll
    for (int l = 0; l < 2; l++) {
        const float* W1 = &sm[OFF_W1 + l * 640];
        const float* b1 = &sm[OFF_B1 + l * 64];
        const float* W2 = &sm[OFF_W2 + l * 768];
        const float* b2 = &sm[OFF_B2 + l * 12];

        // ---- attention block: fully sample-packed matvec, residual folded into init ----
        ln10p(sP, nP);
        {
            u64 acc[10];
            const u64* abd = reinterpret_cast<const u64*>(&sm[OFF_ABD + l * 20]);
#pragma unroll
            for (int j = 0; j < 10; j++) acc[j] = add2_(sP[j], abd[j]);
#pragma unroll
            for (int i = 0; i < 10; i++) {
                const ulonglong2* ar = reinterpret_cast<const ulonglong2*>(&sm[OFF_AD + l * 200 + i * 20]);
                ulonglong2 a01 = ar[0], a23 = ar[1], a45 = ar[2], a67 = ar[3], a89 = ar[4];
                acc[0] = fma2_(nP[i], a01.x, acc[0]);
                acc[1] = fma2_(nP[i], a01.y, acc[1]);
                acc[2] = fma2_(nP[i], a23.x, acc[2]);
                acc[3] = fma2_(nP[i], a23.y, acc[3]);
                acc[4] = fma2_(nP[i], a45.x, acc[4]);
                acc[5] = fma2_(nP[i], a45.y, acc[5]);
                acc[6] = fma2_(nP[i], a67.x, acc[6]);
                acc[7] = fma2_(nP[i], a67.y, acc[7]);
                acc[8] = fma2_(nP[i], a89.x, acc[8]);
                acc[9] = fma2_(nP[i], a89.y, acc[9]);
            }
#pragma unroll
            for (int j = 0; j < 10; j++) sP[j] = acc[j];
        }

        // ---- FFN block (output-packed per sample) ----
        ln10p(sP, nP);
        u64 nbA[10], nbB[10];
#pragma unroll
        for (int i = 0; i < 10; i++) {
            float lo, hi; upk2(nP[i], lo, hi);
            nbA[i] = pk2(lo, lo); nbB[i] = pk2(hi, hi);
        }
        u64 accA[5], accB[5];
#pragma unroll
        for (int p = 0; p < 5; p++) {
            u64 b = *reinterpret_cast<const u64*>(&b2[2 * p]);
            accA[p] = b; accB[p] = b;
        }
#pragma unroll 1
        for (int f = 0; f < 64; f += 4) {
            u64 bb01 = *reinterpret_cast<const u64*>(&b1[f]);
            u64 bb23 = *reinterpret_cast<const u64*>(&b1[f + 2]);
            u64 tA01 = bb01, tA23 = bb23, tB01 = bb01, tB23 = bb23;
#pragma unroll
            for (int i = 0; i < 10; i++) {
                ulonglong2 w = *reinterpret_cast<const ulonglong2*>(&W1[i * 64 + f]);
                tA01 = fma2_(nbA[i], w.x, tA01);  tB01 = fma2_(nbB[i], w.x, tB01);
                tA23 = fma2_(nbA[i], w.y, tA23);  tB23 = fma2_(nbB[i], w.y, tB23);
            }
            u64 gA01 = gelu2(tA01), gA23 = gelu2(tA23);
            u64 gB01 = gelu2(tB01), gB23 = gelu2(tB23);
            float gA[4], gB[4];
            upk2(gA01, gA[0], gA[1]); upk2(gA23, gA[2], gA[3]);
            upk2(gB01, gB[0], gB[1]); upk2(gB23, gB[2], gB[3]);
#pragma unroll
            for (int fi = 0; fi < 4; fi++) {
                u64 ggA = pk2(gA[fi], gA[fi]);
                u64 ggB = pk2(gB[fi], gB[fi]);
                const ulonglong2* wr = reinterpret_cast<const ulonglong2*>(&W2[(f + fi) * 12]);
                ulonglong2 w01 = wr[0];
                ulonglong2 w23 = wr[1];
                u64 w4 = *reinterpret_cast<const u64*>(&W2[(f + fi) * 12 + 8]);
                accA[0] = fma2_(ggA, w01.x, accA[0]);  accB[0] = fma2_(ggB, w01.x, accB[0]);
                accA[1] = fma2_(ggA, w01.y, accA[1]);  accB[1] = fma2_(ggB, w01.y, accB[1]);
                accA[2] = fma2_(ggA, w23.x, accA[2]);  accB[2] = fma2_(ggB, w23.x, accB[2]);
                accA[3] = fma2_(ggA, w23.y, accA[3]);  accB[3] = fma2_(ggB, w23.y, accB[3]);
                accA[4] = fma2_(ggA, w4,    accA[4]);  accB[4] = fma2_(ggB, w4,    accB[4]);
            }
        }
#pragma unroll
        for (int p = 0; p < 5; p++) {
            float a0, a1, b0, b1v;
            upk2(accA[p], a0, a1); upk2(accB[p], b0, b1v);
            sP[2 * p]     = add2_(sP[2 * p],     pk2(a0, b0));
            sP[2 * p + 1] = add2_(sP[2 * p + 1], pk2(a1, b1v));
        }
    }

    // classifier: lp accumulates -L2E*logit; sigma = 1/(1+exp2(lp))
    float bcn = sm[OFF_BCN];
    u64 lp = pk2(bcn, bcn);
#pragma unroll
    for (int j = 0; j < 10; j++) {
        u64 wc = *reinterpret_cast<const u64*>(&sm[OFF_WCN + 2 * j]);
        lp = fma2_(sP[j], wc, lp);
    }
    float lA, lB; upk2(lp, lA, lB);
    float oA = 1.0f / (1.0f + ex2_a(lA));
    float oB = 1.0f / (1.0f + ex2_a(lB));
    if (haveB) {
        *reinterpret_cast<float2*>(out + i0) = make_float2(oA, oB);
    } else {
        out[i0] = oA;
    }
}

// ---------------- launch ----------------
extern "C" void kernel_launch(void* const* d_in, const int* in_sizes, int n_in,
                              void* d_out, int out_size)
{
    const float* x = (const float*)d_in[0];
    int B = in_sizes[0] / 8;

    // input order: x, prototypes, Wq, bq, Wk, bk, Wv, bv, Wo, bo,
    //              ln1_g, ln1_b, ln2_g, ln2_b, W1, b1, W2, b2, Wc, bc
    fold_kernel<<<1, 256>>>(
        (const float*)d_in[1],                           // prototypes
        (const float*)d_in[6],  (const float*)d_in[7],   // Wv, bv
        (const float*)d_in[8],  (const float*)d_in[9],   // Wo, bo
        (const float*)d_in[10], (const float*)d_in[11],  // ln1_g, ln1_b
        (const float*)d_in[12], (const float*)d_in[13],  // ln2_g, ln2_b
        (const float*)d_in[14], (const float*)d_in[15],  // W1, b1
        (const float*)d_in[16], (const float*)d_in[17],  // W2, b2
        (const float*)d_in[18], (const float*)d_in[19]); // Wc, bc

    int pairs = (B + 1) / 2;
    fwd_kernel<<<(pairs + 255) / 256, 256>>>(x, (float*)d_out, B);
}

// round 9
// speedup vs baseline: 1.6123x; 1.6123x over previous
#include <cuda_runtime.h>
#include <cstdint>

typedef unsigned long long u64;

#define L2E 1.4426950408889634f

// ---------------- folded-parameter block layout (floats) ----------------
#define OFF_PDS 0     // 10 x 8 pairs: prototypes dup, scaled by 2*L2E (160)
#define OFF_PPL 160   // 10 pairs: -L2E * |p|^2 (20)
#define OFF_A   180   // 2 x 10 x 12 row-padded: diag(ln1_g) @ Wv @ Wo (240)
#define OFF_AB  420   // 2 x 12: folded attn bias (24)
#define OFF_W1  444   // 2 x 10 x 64: diag(ln2_g) @ W1 (1280)
#define OFF_B1  1724  // 2 x 64: b1 + ln2_b @ W1 (128) -> ends 1852
#define OFF_W2  1852  // 2 x 64 x 12 row-padded (1536) -> ends 3388
#define OFF_B2  3388  // 2 x 12 (24)
#define OFF_WCN 3412  // 10 pairs: -L2E * Wc (20)
#define OFF_BCN 3432  // 1: -L2E * bc
#define NPAR    3436

__device__ float g_par[NPAR];

// ---------------- packed f32x2 helpers ----------------
__device__ __forceinline__ u64 pk2(float lo, float hi) {
    u64 r; asm("mov.b64 %0,{%1,%2};" : "=l"(r) : "f"(lo), "f"(hi)); return r;
}
__device__ __forceinline__ void upk2(u64 v, float& lo, float& hi) {
    asm("mov.b64 {%0,%1},%2;" : "=f"(lo), "=f"(hi) : "l"(v));
}
__device__ __forceinline__ u64 fma2_(u64 a, u64 b, u64 c) {
    u64 d; asm("fma.rn.f32x2 %0,%1,%2,%3;" : "=l"(d) : "l"(a), "l"(b), "l"(c)); return d;
}
__device__ __forceinline__ u64 mul2_(u64 a, u64 b) {
    u64 d; asm("mul.rn.f32x2 %0,%1,%2;" : "=l"(d) : "l"(a), "l"(b)); return d;
}
__device__ __forceinline__ u64 add2_(u64 a, u64 b) {
    u64 d; asm("add.rn.f32x2 %0,%1,%2;" : "=l"(d) : "l"(a), "l"(b)); return d;
}
__device__ __forceinline__ float tanh_a(float u) {
    float th; asm("tanh.approx.f32 %0,%1;" : "=f"(th) : "f"(u)); return th;
}
__device__ __forceinline__ float ex2_a(float u) {
    float r; asm("ex2.approx.f32 %0,%1;" : "=f"(r) : "f"(u)); return r;
}

// Packed tanh-gelu: gelu(t) = ht + ht*tanh(u), ht=0.5t, u=t*(K0+K1*t^2)
__device__ __forceinline__ u64 gelu2(u64 t) {
    const u64 K1   = pk2(0.03567740814f, 0.03567740814f);
    const u64 K0   = pk2(0.7978845608f,  0.7978845608f);
    const u64 HALF = pk2(0.5f, 0.5f);
    u64 tt = mul2_(t, t);
    u64 in = fma2_(tt, K1, K0);
    u64 u  = mul2_(t, in);
    float u0, u1; upk2(u, u0, u1);
    u64 th = pk2(tanh_a(u0), tanh_a(u1));
    u64 ht = mul2_(t, HALF);
    return fma2_(ht, th, ht);
}

// Sample-packed LayerNorm over 10 features.
__device__ __forceinline__ void ln10p(const u64* sP, u64* nP) {
    const u64 TENTH = pk2(0.1f, 0.1f);
    const u64 NEG1  = pk2(-1.0f, -1.0f);
    u64 m01 = add2_(sP[0], sP[1]);
    u64 m23 = add2_(sP[2], sP[3]);
    u64 m45 = add2_(sP[4], sP[5]);
    u64 m67 = add2_(sP[6], sP[7]);
    u64 m89 = add2_(sP[8], sP[9]);
    u64 mu = add2_(add2_(add2_(m01, m23), add2_(m45, m67)), m89);
    mu = mul2_(mu, TENTH);
    u64 nmu = mul2_(mu, NEG1);
    u64 d[10];
#pragma unroll
    for (int j = 0; j < 10; j++) d[j] = add2_(sP[j], nmu);
    u64 v = mul2_(d[0], d[0]);
#pragma unroll
    for (int j = 1; j < 10; j++) v = fma2_(d[j], d[j], v);
    v = mul2_(v, TENTH);
    float vA, vB; upk2(v, vA, vB);
    u64 rp = pk2(rsqrtf(vA + 1e-5f), rsqrtf(vB + 1e-5f));
#pragma unroll
    for (int j = 0; j < 10; j++) nP[j] = mul2_(d[j], rp);
}

// ---------------- one-time weight folding ----------------
// seq-len==1 => softmax(1x1)==1 => attention output == V:
//   seq += LN1(seq) @ (diag(g1) Wv Wo) + (b1ln @ (Wv Wo) + bv @ Wo + bo)
__global__ void fold_kernel(
    const float* __restrict__ proto,
    const float* __restrict__ Wv, const float* __restrict__ bv,
    const float* __restrict__ Wo, const float* __restrict__ bo,
    const float* __restrict__ g1, const float* __restrict__ b1ln,
    const float* __restrict__ g2, const float* __restrict__ b2ln,
    const float* __restrict__ W1, const float* __restrict__ b1,
    const float* __restrict__ W2, const float* __restrict__ b2,
    const float* __restrict__ Wc, const float* __restrict__ bc)
{
    int t = threadIdx.x;
    for (int i = t; i < NPAR; i += 256) g_par[i] = 0.0f;
    __syncthreads();

    for (int i = t; i < 80; i += 256) {
        float v = 2.0f * L2E * proto[i];
        g_par[OFF_PDS + 2 * i] = v;
        g_par[OFF_PDS + 2 * i + 1] = v;
    }
    if (t < 10) {
        float s = 0.0f;
        for (int d = 0; d < 8; d++) s += proto[t * 8 + d] * proto[t * 8 + d];
        g_par[OFF_PPL + 2 * t] = -L2E * s;
        g_par[OFF_PPL + 2 * t + 1] = -L2E * s;
    }
#pragma unroll
    for (int l = 0; l < 2; l++) {
        if (t < 100) {
            int i = t / 10, j = t % 10;
            float m = 0.0f;
            for (int k = 0; k < 10; k++) m += Wv[l * 100 + i * 10 + k] * Wo[l * 100 + k * 10 + j];
            g_par[OFF_A + l * 120 + i * 12 + j] = g1[l * 10 + i] * m;
        }
        if (t < 10) {  // folded attention bias, j = t
            float s = bo[l * 10 + t];
            for (int k = 0; k < 10; k++) s += bv[l * 10 + k] * Wo[l * 100 + k * 10 + t];
            for (int i = 0; i < 10; i++) {
                float m = 0.0f;
                for (int k = 0; k < 10; k++) m += Wv[l * 100 + i * 10 + k] * Wo[l * 100 + k * 10 + t];
                s += b1ln[l * 10 + i] * m;
            }
            g_par[OFF_AB + l * 12 + t] = s;
        }
        for (int e = t; e < 640; e += 256) {
            int i = e / 64;
            g_par[OFF_W1 + l * 640 + e] = g2[l * 10 + i] * W1[l * 640 + e];
        }
        if (t < 64) {
            float s = b1[l * 64 + t];
            for (int i = 0; i < 10; i++) s += b2ln[l * 10 + i] * W1[l * 640 + i * 64 + t];
            g_par[OFF_B1 + l * 64 + t] = s;
        }
        for (int e = t; e < 640; e += 256) {
            int f = e / 10, j = e % 10;
            g_par[OFF_W2 + l * 768 + f * 12 + j] = W2[l * 640 + e];
        }
        if (t < 10) g_par[OFF_B2 + l * 12 + t] = b2[l * 10 + t];
    }
    if (t < 10) {
        float w = -L2E * Wc[t];
        g_par[OFF_WCN + 2 * t] = w;
        g_par[OFF_WCN + 2 * t + 1] = w;
    }
    if (t == 0) g_par[OFF_BCN] = -L2E * bc[0];
}

// ---------------- main kernel: 2 samples per thread, sample-packed state ----------------
__global__ void __launch_bounds__(256) fwd_kernel(
    const float* __restrict__ x, float* __restrict__ out, int B)
{
    __shared__ __align__(16) float sm[NPAR];
    for (int i = threadIdx.x; i < NPAR; i += 256) sm[i] = g_par[i];
    __syncthreads();

    int pid = blockIdx.x * 256 + threadIdx.x;   // pair id
    int i0 = pid * 2;
    if (i0 >= B) return;
    bool haveB = (i0 + 1 < B);

    const float4* xp = reinterpret_cast<const float4*>(x) + (u64)i0 * 2;
    float4 xa0 = xp[0], xb0 = xp[1];
    float4 xa1 = haveB ? xp[2] : xa0;
    float4 xb1 = haveB ? xp[3] : xb0;

    const u64 NL2E = pk2(-L2E, -L2E);

    // sample-packed input components
    u64 X[8];
    X[0] = pk2(xa0.x, xa1.x); X[1] = pk2(xa0.y, xa1.y);
    X[2] = pk2(xa0.z, xa1.z); X[3] = pk2(xa0.w, xa1.w);
    X[4] = pk2(xb0.x, xb1.x); X[5] = pk2(xb0.y, xb1.y);
    X[6] = pk2(xb0.z, xb1.z); X[7] = pk2(xb0.w, xb1.w);

    u64 x2p = mul2_(X[0], X[0]);
#pragma unroll
    for (int c = 1; c < 8; c++) x2p = fma2_(X[c], X[c], x2p);
    u64 nx2L = mul2_(x2p, NL2E);   // -L2E * |x|^2 (packed)

    // RBF: exp2( L2E*(2 x.p - |x|^2 - |p|^2) ); all scales pre-folded
    u64 sP[10];
#pragma unroll
    for (int j = 0; j < 10; j++) {
        const u64* pd = reinterpret_cast<const u64*>(&sm[OFF_PDS + j * 16]);
        u64 dp = mul2_(X[0], pd[0]);
#pragma unroll
        for (int c = 1; c < 8; c++) dp = fma2_(X[c], pd[c], dp);
        u64 pre = *reinterpret_cast<const u64*>(&sm[OFF_PPL + 2 * j]);
        u64 arg = add2_(dp, add2_(nx2L, pre));
        float a0, a1; upk2(arg, a0, a1);
        sP[j] = pk2(ex2_a(a0), ex2_a(a1));
    }

    u64 nP[10], nbA[10], nbB[10];
    u64 accA[5], accB[5];

#pragma unroll
    for (int l = 0; l < 2; l++) {
        const float* A  = &sm[OFF_A  + l * 120];
        const float* aB = &sm[OFF_AB + l * 12];
        const float* W1 = &sm[OFF_W1 + l * 640];
        const float* b1 = &sm[OFF_B1 + l * 64];
        const float* W2 = &sm[OFF_W2 + l * 768];
        const float* b2 = &sm[OFF_B2 + l * 12];

        // ---- attention block (collapsed to folded 10x10 matvec) ----
        ln10p(sP, nP);
#pragma unroll
        for (int i = 0; i < 10; i++) {
            float lo, hi; upk2(nP[i], lo, hi);
            nbA[i] = pk2(lo, lo); nbB[i] = pk2(hi, hi);
        }
#pragma unroll
        for (int p = 0; p < 5; p++) {
            u64 b = *reinterpret_cast<const u64*>(&aB[2 * p]);
            accA[p] = b; accB[p] = b;
        }
#pragma unroll
        for (int i = 0; i < 10; i++) {
            const ulonglong2* ar = reinterpret_cast<const ulonglong2*>(&A[i * 12]);
            ulonglong2 a01 = ar[0];
            ulonglong2 a23 = ar[1];
            u64 a4 = *reinterpret_cast<const u64*>(&A[i * 12 + 8]);
            accA[0] = fma2_(nbA[i], a01.x, accA[0]);  accB[0] = fma2_(nbB[i], a01.x, accB[0]);
            accA[1] = fma2_(nbA[i], a01.y, accA[1]);  accB[1] = fma2_(nbB[i], a01.y, accB[1]);
            accA[2] = fma2_(nbA[i], a23.x, accA[2]);  accB[2] = fma2_(nbB[i], a23.x, accB[2]);
            accA[3] = fma2_(nbA[i], a23.y, accA[3]);  accB[3] = fma2_(nbB[i], a23.y, accB[3]);
            accA[4] = fma2_(nbA[i], a4,    accA[4]);  accB[4] = fma2_(nbB[i], a4,    accB[4]);
        }
#pragma unroll
        for (int p = 0; p < 5; p++) {
            float a0, a1, b0, b1v;
            upk2(accA[p], a0, a1); upk2(accB[p], b0, b1v);
            sP[2 * p]     = add2_(sP[2 * p],     pk2(a0, b0));
            sP[2 * p + 1] = add2_(sP[2 * p + 1], pk2(a1, b1v));
        }

        // ---- FFN block ----
        ln10p(sP, nP);
#pragma unroll
        for (int i = 0; i < 10; i++) {
            float lo, hi; upk2(nP[i], lo, hi);
            nbA[i] = pk2(lo, lo); nbB[i] = pk2(hi, hi);
        }
#pragma unroll
        for (int p = 0; p < 5; p++) {
            u64 b = *reinterpret_cast<const u64*>(&b2[2 * p]);
            accA[p] = b; accB[p] = b;
        }
#pragma unroll 1
        for (int f = 0; f < 64; f += 4) {
            u64 bb01 = *reinterpret_cast<const u64*>(&b1[f]);
            u64 bb23 = *reinterpret_cast<const u64*>(&b1[f + 2]);
            u64 tA01 = bb01, tA23 = bb23, tB01 = bb01, tB23 = bb23;
#pragma unroll
            for (int i = 0; i < 10; i++) {
                ulonglong2 w = *reinterpret_cast<const ulonglong2*>(&W1[i * 64 + f]);
                tA01 = fma2_(nbA[i], w.x, tA01);  tB01 = fma2_(nbB[i], w.x, tB01);
                tA23 = fma2_(nbA[i], w.y, tA23);  tB23 = fma2_(nbB[i], w.y, tB23);
            }
            u64 gA01 = gelu2(tA01), gA23 = gelu2(tA23);
            u64 gB01 = gelu2(tB01), gB23 = gelu2(tB23);
            float gA[4], gB[4];
            upk2(gA01, gA[0], gA[1]); upk2(gA23, gA[2], gA[3]);
            upk2(gB01, gB[0], gB[1]); upk2(gB23, gB[2], gB[3]);
#pragma unroll
            for (int fi = 0; fi < 4; fi++) {
                u64 ggA = pk2(gA[fi], gA[fi]);
                u64 ggB = pk2(gB[fi], gB[fi]);
                const ulonglong2* wr = reinterpret_cast<const ulonglong2*>(&W2[(f + fi) * 12]);
                ulonglong2 w01 = wr[0];
                ulonglong2 w23 = wr[1];
                u64 w4 = *reinterpret_cast<const u64*>(&W2[(f + fi) * 12 + 8]);
                accA[0] = fma2_(ggA, w01.x, accA[0]);  accB[0] = fma2_(ggB, w01.x, accB[0]);
                accA[1] = fma2_(ggA, w01.y, accA[1]);  accB[1] = fma2_(ggB, w01.y, accB[1]);
                accA[2] = fma2_(ggA, w23.x, accA[2]);  accB[2] = fma2_(ggB, w23.x, accB[2]);
                accA[3] = fma2_(ggA, w23.y, accA[3]);  accB[3] = fma2_(ggB, w23.y, accB[3]);
                accA[4] = fma2_(ggA, w4,    accA[4]);  accB[4] = fma2_(ggB, w4,    accB[4]);
            }
        }
#pragma unroll
        for (int p = 0; p < 5; p++) {
            float a0, a1, b0, b1v;
            upk2(accA[p], a0, a1); upk2(accB[p], b0, b1v);
            sP[2 * p]     = add2_(sP[2 * p],     pk2(a0, b0));
            sP[2 * p + 1] = add2_(sP[2 * p + 1], pk2(a1, b1v));
        }
    }

    // classifier: lp accumulates -L2E*logit; sigma = 1/(1+exp2(lp))
    float bcn = sm[OFF_BCN];
    u64 lp = pk2(bcn, bcn);
#pragma unroll
    for (int j = 0; j < 10; j++) {
        u64 wc = *reinterpret_cast<const u64*>(&sm[OFF_WCN + 2 * j]);
        lp = fma2_(sP[j], wc, lp);
    }
    float lA, lB; upk2(lp, lA, lB);
    float oA = 1.0f / (1.0f + ex2_a(lA));
    float oB = 1.0f / (1.0f + ex2_a(lB));
    if (haveB) {
        *reinterpret_cast<float2*>(out + i0) = make_float2(oA, oB);
    } else {
        out[i0] = oA;
    }
}

// ---------------- launch ----------------
extern "C" void kernel_launch(void* const* d_in, const int* in_sizes, int n_in,
                              void* d_out, int out_size)
{
    const float* x = (const float*)d_in[0];
    int B = in_sizes[0] / 8;

    // input order: x, prototypes, Wq, bq, Wk, bk, Wv, bv, Wo, bo,
    //              ln1_g, ln1_b, ln2_g, ln2_b, W1, b1, W2, b2, Wc, bc
    fold_kernel<<<1, 256>>>(
        (const float*)d_in[1],                           // prototypes
        (const float*)d_in[6],  (const float*)d_in[7],   // Wv, bv
        (const float*)d_in[8],  (const float*)d_in[9],   // Wo, bo
        (const float*)d_in[10], (const float*)d_in[11],  // ln1_g, ln1_b
        (const float*)d_in[12], (const float*)d_in[13],  // ln2_g, ln2_b
        (const float*)d_in[14], (const float*)d_in[15],  // W1, b1
        (const float*)d_in[16], (const float*)d_in[17],  // W2, b2
        (const float*)d_in[18], (const float*)d_in[19]); // Wc, bc

    int pairs = (B + 1) / 2;
    fwd_kernel<<<(pairs + 255) / 256, 256>>>(x, (float*)d_out, B);
}

// round 12
// speedup vs baseline: 1.6281x; 1.0098x over previous
#include <cuda_runtime.h>
#include <cstdint>

typedef unsigned long long u64;

#define L2E 1.4426950408889634f

// ---------------- folded-parameter block layout (floats) ----------------
#define OFF_PDS 0     // 10 x 8 pairs: prototypes dup, scaled by 2*L2E (160)
#define OFF_PPL 160   // 10 pairs: -L2E * |p|^2 (20)
#define OFF_A   180   // 2 x 10 x 12 row-padded: diag(ln1_g) @ Wv @ Wo (240)
#define OFF_AB  420   // 2 x 12: folded attn bias (24)
#define OFF_W1  444   // 2 x 10 x 64: diag(ln2_g) @ W1 (1280)
#define OFF_B1  1724  // 2 x 64: b1 + ln2_b @ W1 (128) -> ends 1852
#define OFF_W2  1852  // 2 x 64 x 12 row-padded (1536) -> ends 3388
#define OFF_B2  3388  // 2 x 12 (24)
#define OFF_WCN 3412  // 10 pairs: -L2E * Wc (20)
#define OFF_BCN 3432  // 1: -L2E * bc
#define NPAR    3436

__device__ float g_par[NPAR];

// ---------------- packed f32x2 helpers ----------------
__device__ __forceinline__ u64 pk2(float lo, float hi) {
    u64 r; asm("mov.b64 %0,{%1,%2};" : "=l"(r) : "f"(lo), "f"(hi)); return r;
}
__device__ __forceinline__ void upk2(u64 v, float& lo, float& hi) {
    asm("mov.b64 {%0,%1},%2;" : "=f"(lo), "=f"(hi) : "l"(v));
}
__device__ __forceinline__ u64 fma2_(u64 a, u64 b, u64 c) {
    u64 d; asm("fma.rn.f32x2 %0,%1,%2,%3;" : "=l"(d) : "l"(a), "l"(b), "l"(c)); return d;
}
__device__ __forceinline__ u64 mul2_(u64 a, u64 b) {
    u64 d; asm("mul.rn.f32x2 %0,%1,%2;" : "=l"(d) : "l"(a), "l"(b)); return d;
}
__device__ __forceinline__ u64 add2_(u64 a, u64 b) {
    u64 d; asm("add.rn.f32x2 %0,%1,%2;" : "=l"(d) : "l"(a), "l"(b)); return d;
}
__device__ __forceinline__ float tanh_a(float u) {
    float th; asm("tanh.approx.f32 %0,%1;" : "=f"(th) : "f"(u)); return th;
}
__device__ __forceinline__ float ex2_a(float u) {
    float r; asm("ex2.approx.f32 %0,%1;" : "=f"(r) : "f"(u)); return r;
}

// Packed tanh-gelu: gelu(t) = ht + ht*tanh(u), ht=0.5t, u=t*(K0+K1*t^2)
__device__ __forceinline__ u64 gelu2(u64 t) {
    const u64 K1   = pk2(0.03567740814f, 0.03567740814f);
    const u64 K0   = pk2(0.7978845608f,  0.7978845608f);
    const u64 HALF = pk2(0.5f, 0.5f);
    u64 tt = mul2_(t, t);
    u64 in = fma2_(tt, K1, K0);
    u64 u  = mul2_(t, in);
    float u0, u1; upk2(u, u0, u1);
    u64 th = pk2(tanh_a(u0), tanh_a(u1));
    u64 ht = mul2_(t, HALF);
    return fma2_(ht, th, ht);
}

// Sample-packed LayerNorm over 10 features.
__device__ __forceinline__ void ln10p(const u64* sP, u64* nP) {
    const u64 TENTH = pk2(0.1f, 0.1f);
    const u64 NEG1  = pk2(-1.0f, -1.0f);
    u64 m01 = add2_(sP[0], sP[1]);
    u64 m23 = add2_(sP[2], sP[3]);
    u64 m45 = add2_(sP[4], sP[5]);
    u64 m67 = add2_(sP[6], sP[7]);
    u64 m89 = add2_(sP[8], sP[9]);
    u64 mu = add2_(add2_(add2_(m01, m23), add2_(m45, m67)), m89);
    mu = mul2_(mu, TENTH);
    u64 nmu = mul2_(mu, NEG1);
    u64 d[10];
#pragma unroll
    for (int j = 0; j < 10; j++) d[j] = add2_(sP[j], nmu);
    u64 v = mul2_(d[0], d[0]);
#pragma unroll
    for (int j = 1; j < 10; j++) v = fma2_(d[j], d[j], v);
    v = mul2_(v, TENTH);
    float vA, vB; upk2(v, vA, vB);
    u64 rp = pk2(rsqrtf(vA + 1e-5f), rsqrtf(vB + 1e-5f));
#pragma unroll
    for (int j = 0; j < 10; j++) nP[j] = mul2_(d[j], rp);
}

// ---------------- one-time weight folding ----------------
// seq-len==1 => softmax(1x1)==1 => attention output == V:
//   seq += LN1(seq) @ (diag(g1) Wv Wo) + (b1ln @ (Wv Wo) + bv @ Wo + bo)
__global__ void fold_kernel(
    const float* __restrict__ proto,
    const float* __restrict__ Wv, const float* __restrict__ bv,
    const float* __restrict__ Wo, const float* __restrict__ bo,
    const float* __restrict__ g1, const float* __restrict__ b1ln,
    const float* __restrict__ g2, const float* __restrict__ b2ln,
    const float* __restrict__ W1, const float* __restrict__ b1,
    const float* __restrict__ W2, const float* __restrict__ b2,
    const float* __restrict__ Wc, const float* __restrict__ bc)
{
    int t = threadIdx.x;
    for (int i = t; i < NPAR; i += 256) g_par[i] = 0.0f;
    __syncthreads();

    for (int i = t; i < 80; i += 256) {
        float v = 2.0f * L2E * proto[i];
        g_par[OFF_PDS + 2 * i] = v;
        g_par[OFF_PDS + 2 * i + 1] = v;
    }
    if (t < 10) {
        float s = 0.0f;
        for (int d = 0; d < 8; d++) s += proto[t * 8 + d] * proto[t * 8 + d];
        g_par[OFF_PPL + 2 * t] = -L2E * s;
        g_par[OFF_PPL + 2 * t + 1] = -L2E * s;
    }
#pragma unroll
    for (int l = 0; l < 2; l++) {
        if (t < 100) {
            int i = t / 10, j = t % 10;
            float m = 0.0f;
            for (int k = 0; k < 10; k++) m += Wv[l * 100 + i * 10 + k] * Wo[l * 100 + k * 10 + j];
            g_par[OFF_A + l * 120 + i * 12 + j] = g1[l * 10 + i] * m;
        }
        if (t < 10) {  // folded attention bias, j = t
            float s = bo[l * 10 + t];
            for (int k = 0; k < 10; k++) s += bv[l * 10 + k] * Wo[l * 100 + k * 10 + t];
            for (int i = 0; i < 10; i++) {
                float m = 0.0f;
                for (int k = 0; k < 10; k++) m += Wv[l * 100 + i * 10 + k] * Wo[l * 100 + k * 10 + t];
                s += b1ln[l * 10 + i] * m;
            }
            g_par[OFF_AB + l * 12 + t] = s;
        }
        for (int e = t; e < 640; e += 256) {
            int i = e / 64;
            g_par[OFF_W1 + l * 640 + e] = g2[l * 10 + i] * W1[l * 640 + e];
        }
        if (t < 64) {
            float s = b1[l * 64 + t];
            for (int i = 0; i < 10; i++) s += b2ln[l * 10 + i] * W1[l * 640 + i * 64 + t];
            g_par[OFF_B1 + l * 64 + t] = s;
        }
        for (int e = t; e < 640; e += 256) {
            int f = e / 10, j = e % 10;
            g_par[OFF_W2 + l * 768 + f * 12 + j] = W2[l * 640 + e];
        }
        if (t < 10) g_par[OFF_B2 + l * 12 + t] = b2[l * 10 + t];
    }
    if (t < 10) {
        float w = -L2E * Wc[t];
        g_par[OFF_WCN + 2 * t] = w;
        g_par[OFF_WCN + 2 * t + 1] = w;
    }
    if (t == 0) g_par[OFF_BCN] = -L2E * bc[0];
}

// ---------------- main kernel: 2 samples per thread, sample-packed state ----------------
__global__ void __launch_bounds__(256, 2) fwd_kernel(
    const float* __restrict__ x, float* __restrict__ out, int B)
{
    __shared__ __align__(16) float sm[NPAR];
    for (int i = threadIdx.x; i < NPAR; i += 256) sm[i] = g_par[i];
    __syncthreads();

    int pid = blockIdx.x * 256 + threadIdx.x;   // pair id
    int i0 = pid * 2;
    if (i0 >= B) return;
    bool haveB = (i0 + 1 < B);

    const float4* xp = reinterpret_cast<const float4*>(x) + (u64)i0 * 2;
    float4 xa0 = xp[0], xb0 = xp[1];
    float4 xa1 = haveB ? xp[2] : xa0;
    float4 xb1 = haveB ? xp[3] : xb0;

    const u64 NL2E = pk2(-L2E, -L2E);

    // sample-packed input components
    u64 X[8];
    X[0] = pk2(xa0.x, xa1.x); X[1] = pk2(xa0.y, xa1.y);
    X[2] = pk2(xa0.z, xa1.z); X[3] = pk2(xa0.w, xa1.w);
    X[4] = pk2(xb0.x, xb1.x); X[5] = pk2(xb0.y, xb1.y);
    X[6] = pk2(xb0.z, xb1.z); X[7] = pk2(xb0.w, xb1.w);

    u64 x2p = mul2_(X[0], X[0]);
#pragma unroll
    for (int c = 1; c < 8; c++) x2p = fma2_(X[c], X[c], x2p);
    u64 nx2L = mul2_(x2p, NL2E);   // -L2E * |x|^2 (packed)

    // RBF: exp2( L2E*(2 x.p - |x|^2 - |p|^2) ); all scales pre-folded
    u64 sP[10];
#pragma unroll
    for (int j = 0; j < 10; j++) {
        const u64* pd = reinterpret_cast<const u64*>(&sm[OFF_PDS + j * 16]);
        u64 dp = mul2_(X[0], pd[0]);
#pragma unroll
        for (int c = 1; c < 8; c++) dp = fma2_(X[c], pd[c], dp);
        u64 pre = *reinterpret_cast<const u64*>(&sm[OFF_PPL + 2 * j]);
        u64 arg = add2_(dp, add2_(nx2L, pre));
        float a0, a1; upk2(arg, a0, a1);
        sP[j] = pk2(ex2_a(a0), ex2_a(a1));
    }

    u64 nP[10], nbA[10], nbB[10];
    u64 accA[5], accB[5];

#pragma unroll
    for (int l = 0; l < 2; l++) {
        const float* A  = &sm[OFF_A  + l * 120];
        const float* aB = &sm[OFF_AB + l * 12];
        const float* W1 = &sm[OFF_W1 + l * 640];
        const float* b1 = &sm[OFF_B1 + l * 64];
        const float* W2 = &sm[OFF_W2 + l * 768];
        const float* b2 = &sm[OFF_B2 + l * 12];

        // ---- attention block (collapsed to folded 10x10 matvec) ----
        ln10p(sP, nP);
#pragma unroll
        for (int i = 0; i < 10; i++) {
            float lo, hi; upk2(nP[i], lo, hi);
            nbA[i] = pk2(lo, lo); nbB[i] = pk2(hi, hi);
        }
#pragma unroll
        for (int p = 0; p < 5; p++) {
            u64 b = *reinterpret_cast<const u64*>(&aB[2 * p]);
            accA[p] = b; accB[p] = b;
        }
#pragma unroll
        for (int i = 0; i < 10; i++) {
            const ulonglong2* ar = reinterpret_cast<const ulonglong2*>(&A[i * 12]);
            ulonglong2 a01 = ar[0];
            ulonglong2 a23 = ar[1];
            u64 a4 = *reinterpret_cast<const u64*>(&A[i * 12 + 8]);
            accA[0] = fma2_(nbA[i], a01.x, accA[0]);  accB[0] = fma2_(nbB[i], a01.x, accB[0]);
            accA[1] = fma2_(nbA[i], a01.y, accA[1]);  accB[1] = fma2_(nbB[i], a01.y, accB[1]);
            accA[2] = fma2_(nbA[i], a23.x, accA[2]);  accB[2] = fma2_(nbB[i], a23.x, accB[2]);
            accA[3] = fma2_(nbA[i], a23.y, accA[3]);  accB[3] = fma2_(nbB[i], a23.y, accB[3]);
            accA[4] = fma2_(nbA[i], a4,    accA[4]);  accB[4] = fma2_(nbB[i], a4,    accB[4]);
        }
#pragma unroll
        for (int p = 0; p < 5; p++) {
            float a0, a1, b0, b1v;
            upk2(accA[p], a0, a1); upk2(accB[p], b0, b1v);
            sP[2 * p]     = add2_(sP[2 * p],     pk2(a0, b0));
            sP[2 * p + 1] = add2_(sP[2 * p + 1], pk2(a1, b1v));
        }

        // ---- FFN block ----
        ln10p(sP, nP);
#pragma unroll
        for (int i = 0; i < 10; i++) {
            float lo, hi; upk2(nP[i], lo, hi);
            nbA[i] = pk2(lo, lo); nbB[i] = pk2(hi, hi);
        }
#pragma unroll
        for (int p = 0; p < 5; p++) {
            u64 b = *reinterpret_cast<const u64*>(&b2[2 * p]);
            accA[p] = b; accB[p] = b;
        }
        // unroll 2: give the scheduler a cross-iteration window so next
        // group's W1 LDS overlap this group's W2 math / tanh latency.
#pragma unroll 2
        for (int f = 0; f < 64; f += 4) {
            u64 bb01 = *reinterpret_cast<const u64*>(&b1[f]);
            u64 bb23 = *reinterpret_cast<const u64*>(&b1[f + 2]);
            u64 tA01 = bb01, tA23 = bb23, tB01 = bb01, tB23 = bb23;
#pragma unroll
            for (int i = 0; i < 10; i++) {
                ulonglong2 w = *reinterpret_cast<const ulonglong2*>(&W1[i * 64 + f]);
                tA01 = fma2_(nbA[i], w.x, tA01);  tB01 = fma2_(nbB[i], w.x, tB01);
                tA23 = fma2_(nbA[i], w.y, tA23);  tB23 = fma2_(nbB[i], w.y, tB23);
            }
            u64 gA01 = gelu2(tA01), gA23 = gelu2(tA23);
            u64 gB01 = gelu2(tB01), gB23 = gelu2(tB23);
            float gA[4], gB[4];
            upk2(gA01, gA[0], gA[1]); upk2(gA23, gA[2], gA[3]);
            upk2(gB01, gB[0], gB[1]); upk2(gB23, gB[2], gB[3]);
#pragma unroll
            for (int fi = 0; fi < 4; fi++) {
                u64 ggA = pk2(gA[fi], gA[fi]);
                u64 ggB = pk2(gB[fi], gB[fi]);
                const ulonglong2* wr = reinterpret_cast<const ulonglong2*>(&W2[(f + fi) * 12]);
                ulonglong2 w01 = wr[0];
                ulonglong2 w23 = wr[1];
                u64 w4 = *reinterpret_cast<const u64*>(&W2[(f + fi) * 12 + 8]);
                accA[0] = fma2_(ggA, w01.x, accA[0]);  accB[0] = fma2_(ggB, w01.x, accB[0]);
                accA[1] = fma2_(ggA, w01.y, accA[1]);  accB[1] = fma2_(ggB, w01.y, accB[1]);
                accA[2] = fma2_(ggA, w23.x, accA[2]);  accB[2] = fma2_(ggB, w23.x, accB[2]);
                accA[3] = fma2_(ggA, w23.y, accA[3]);  accB[3] = fma2_(ggB, w23.y, accB[3]);
                accA[4] = fma2_(ggA, w4,    accA[4]);  accB[4] = fma2_(ggB, w4,    accB[4]);
            }
        }
#pragma unroll
        for (int p = 0; p < 5; p++) {
            float a0, a1, b0, b1v;
            upk2(accA[p], a0, a1); upk2(accB[p], b0, b1v);
            sP[2 * p]     = add2_(sP[2 * p],     pk2(a0, b0));
            sP[2 * p + 1] = add2_(sP[2 * p + 1], pk2(a1, b1v));
        }
    }

    // classifier: lp accumulates -L2E*logit; sigma = 1/(1+exp2(lp))
    float bcn = sm[OFF_BCN];
    u64 lp = pk2(bcn, bcn);
#pragma unroll
    for (int j = 0; j < 10; j++) {
        u64 wc = *reinterpret_cast<const u64*>(&sm[OFF_WCN + 2 * j]);
        lp = fma2_(sP[j], wc, lp);
    }
    float lA, lB; upk2(lp, lA, lB);
    float oA = 1.0f / (1.0f + ex2_a(lA));
    float oB = 1.0f / (1.0f + ex2_a(lB));
    if (haveB) {
        *reinterpret_cast<float2*>(out + i0) = make_float2(oA, oB);
    } else {
        out[i0] = oA;
    }
}

// ---------------- launch ----------------
extern "C" void kernel_launch(void* const* d_in, const int* in_sizes, int n_in,
                              void* d_out, int out_size)
{
    const float* x = (const float*)d_in[0];
    int B = in_sizes[0] / 8;

    // input order: x, prototypes, Wq, bq, Wk, bk, Wv, bv, Wo, bo,
    //              ln1_g, ln1_b, ln2_g, ln2_b, W1, b1, W2, b2, Wc, bc
    fold_kernel<<<1, 256>>>(
        (const float*)d_in[1],                           // prototypes
        (const float*)d_in[6],  (const float*)d_in[7],   // Wv, bv
        (const float*)d_in[8],  (const float*)d_in[9],   // Wo, bo
        (const float*)d_in[10], (const float*)d_in[11],  // ln1_g, ln1_b
        (const float*)d_in[12], (const float*)d_in[13],  // ln2_g, ln2_b
        (const float*)d_in[14], (const float*)d_in[15],  // W1, b1
        (const float*)d_in[16], (const float*)d_in[17],  // W2, b2
        (const float*)d_in[18], (const float*)d_in[19]); // Wc, bc

    int pairs = (B + 1) / 2;
    fwd_kernel<<<(pairs + 255) / 256, 256>>>(x, (float*)d_out, B);
}

// round 17
// speedup vs baseline: 1.6557x; 1.0170x over previous
#include <cuda_runtime.h>
#include <cstdint>

typedef unsigned long long u64;

#define L2E 1.4426950408889634f

// ---------------- folded-parameter block layout (floats) ----------------
#define OFF_PDS 0     // 10 x 8 pairs: prototypes dup, scaled by 2*L2E (160)
#define OFF_PPL 160   // 10 pairs: -L2E * |p|^2 (20)
#define OFF_A   180   // 2 x 10 x 12 row-padded: diag(ln1_g) @ Wv @ Wo (240)
#define OFF_AB  420   // 2 x 12: folded attn bias (24)
#define OFF_W1  444   // 2 x 10 x 64: diag(ln2_g) @ W1 (1280)
#define OFF_B1  1724  // 2 x 64: b1 + ln2_b @ W1 (128) -> ends 1852
#define OFF_W2  1852  // 2 x 64 x 12 row-padded (1536) -> ends 3388
#define OFF_B2  3388  // 2 x 12 (24)
#define OFF_WCN 3412  // 10 pairs: -L2E * Wc (20)
#define OFF_BCN 3432  // 1: -L2E * bc
#define NPAR    3436

#define BLK 128

__device__ float g_par[NPAR];

// ---------------- packed f32x2 helpers ----------------
__device__ __forceinline__ u64 pk2(float lo, float hi) {
    u64 r; asm("mov.b64 %0,{%1,%2};" : "=l"(r) : "f"(lo), "f"(hi)); return r;
}
__device__ __forceinline__ void upk2(u64 v, float& lo, float& hi) {
    asm("mov.b64 {%0,%1},%2;" : "=f"(lo), "=f"(hi) : "l"(v));
}
__device__ __forceinline__ u64 fma2_(u64 a, u64 b, u64 c) {
    u64 d; asm("fma.rn.f32x2 %0,%1,%2,%3;" : "=l"(d) : "l"(a), "l"(b), "l"(c)); return d;
}
__device__ __forceinline__ u64 mul2_(u64 a, u64 b) {
    u64 d; asm("mul.rn.f32x2 %0,%1,%2;" : "=l"(d) : "l"(a), "l"(b)); return d;
}
__device__ __forceinline__ u64 add2_(u64 a, u64 b) {
    u64 d; asm("add.rn.f32x2 %0,%1,%2;" : "=l"(d) : "l"(a), "l"(b)); return d;
}
__device__ __forceinline__ float tanh_a(float u) {
    float th; asm("tanh.approx.f32 %0,%1;" : "=f"(th) : "f"(u)); return th;
}
__device__ __forceinline__ float ex2_a(float u) {
    float r; asm("ex2.approx.f32 %0,%1;" : "=f"(r) : "f"(u)); return r;
}

// Packed tanh-gelu: gelu(t) = ht + ht*tanh(u), ht=0.5t, u=t*(K0+K1*t^2)
__device__ __forceinline__ u64 gelu2(u64 t) {
    const u64 K1   = pk2(0.03567740814f, 0.03567740814f);
    const u64 K0   = pk2(0.7978845608f,  0.7978845608f);
    const u64 HALF = pk2(0.5f, 0.5f);
    u64 tt = mul2_(t, t);
    u64 in = fma2_(tt, K1, K0);
    u64 u  = mul2_(t, in);
    float u0, u1; upk2(u, u0, u1);
    u64 th = pk2(tanh_a(u0), tanh_a(u1));
    u64 ht = mul2_(t, HALF);
    return fma2_(ht, th, ht);
}

// Sample-packed LayerNorm over 10 features.
__device__ __forceinline__ void ln10p(const u64* sP, u64* nP) {
    const u64 TENTH = pk2(0.1f, 0.1f);
    const u64 NEG1  = pk2(-1.0f, -1.0f);
    u64 m01 = add2_(sP[0], sP[1]);
    u64 m23 = add2_(sP[2], sP[3]);
    u64 m45 = add2_(sP[4], sP[5]);
    u64 m67 = add2_(sP[6], sP[7]);
    u64 m89 = add2_(sP[8], sP[9]);
    u64 mu = add2_(add2_(add2_(m01, m23), add2_(m45, m67)), m89);
    mu = mul2_(mu, TENTH);
    u64 nmu = mul2_(mu, NEG1);
    u64 d[10];
#pragma unroll
    for (int j = 0; j < 10; j++) d[j] = add2_(sP[j], nmu);
    u64 v = mul2_(d[0], d[0]);
#pragma unroll
    for (int j = 1; j < 10; j++) v = fma2_(d[j], d[j], v);
    v = mul2_(v, TENTH);
    float vA, vB; upk2(v, vA, vB);
    u64 rp = pk2(rsqrtf(vA + 1e-5f), rsqrtf(vB + 1e-5f));
#pragma unroll
    for (int j = 0; j < 10; j++) nP[j] = mul2_(d[j], rp);
}

// ---------------- one-time weight folding ----------------
// seq-len==1 => softmax(1x1)==1 => attention output == V:
//   seq += LN1(seq) @ (diag(g1) Wv Wo) + (b1ln @ (Wv Wo) + bv @ Wo + bo)
__global__ void fold_kernel(
    const float* __restrict__ proto,
    const float* __restrict__ Wv, const float* __restrict__ bv,
    const float* __restrict__ Wo, const float* __restrict__ bo,
    const float* __restrict__ g1, const float* __restrict__ b1ln,
    const float* __restrict__ g2, const float* __restrict__ b2ln,
    const float* __restrict__ W1, const float* __restrict__ b1,
    const float* __restrict__ W2, const float* __restrict__ b2,
    const float* __restrict__ Wc, const float* __restrict__ bc)
{
    int t = threadIdx.x;
    for (int i = t; i < NPAR; i += 256) g_par[i] = 0.0f;
    __syncthreads();

    for (int i = t; i < 80; i += 256) {
        float v = 2.0f * L2E * proto[i];
        g_par[OFF_PDS + 2 * i] = v;
        g_par[OFF_PDS + 2 * i + 1] = v;
    }
    if (t < 10) {
        float s = 0.0f;
        for (int d = 0; d < 8; d++) s += proto[t * 8 + d] * proto[t * 8 + d];
        g_par[OFF_PPL + 2 * t] = -L2E * s;
        g_par[OFF_PPL + 2 * t + 1] = -L2E * s;
    }
#pragma unroll
    for (int l = 0; l < 2; l++) {
        if (t < 100) {
            int i = t / 10, j = t % 10;
            float m = 0.0f;
            for (int k = 0; k < 10; k++) m += Wv[l * 100 + i * 10 + k] * Wo[l * 100 + k * 10 + j];
            g_par[OFF_A + l * 120 + i * 12 + j] = g1[l * 10 + i] * m;
        }
        if (t < 10) {  // folded attention bias, j = t
            float s = bo[l * 10 + t];
            for (int k = 0; k < 10; k++) s += bv[l * 10 + k] * Wo[l * 100 + k * 10 + t];
            for (int i = 0; i < 10; i++) {
                float m = 0.0f;
                for (int k = 0; k < 10; k++) m += Wv[l * 100 + i * 10 + k] * Wo[l * 100 + k * 10 + t];
                s += b1ln[l * 10 + i] * m;
            }
            g_par[OFF_AB + l * 12 + t] = s;
        }
        for (int e = t; e < 640; e += 256) {
            int i = e / 64;
            g_par[OFF_W1 + l * 640 + e] = g2[l * 10 + i] * W1[l * 640 + e];
        }
        if (t < 64) {
            float s = b1[l * 64 + t];
            for (int i = 0; i < 10; i++) s += b2ln[l * 10 + i] * W1[l * 640 + i * 64 + t];
            g_par[OFF_B1 + l * 64 + t] = s;
        }
        for (int e = t; e < 640; e += 256) {
            int f = e / 10, j = e % 10;
            g_par[OFF_W2 + l * 768 + f * 12 + j] = W2[l * 640 + e];
        }
        if (t < 10) g_par[OFF_B2 + l * 12 + t] = b2[l * 10 + t];
    }
    if (t < 10) {
        float w = -L2E * Wc[t];
        g_par[OFF_WCN + 2 * t] = w;
        g_par[OFF_WCN + 2 * t + 1] = w;
    }
    if (t == 0) g_par[OFF_BCN] = -L2E * bc[0];
}

// ---------------- main kernel: 2 samples per thread, 128-thr blocks, 5 blocks/SM --------
__global__ void __launch_bounds__(BLK, 5) fwd_kernel(
    const float* __restrict__ x, float* __restrict__ out, int B)
{
    __shared__ __align__(16) float sm[NPAR];
    __shared__ __align__(16) ulonglong2 sc[5][BLK];  // per-thread residual stash
    for (int i = threadIdx.x; i < NPAR; i += BLK) sm[i] = g_par[i];
    __syncthreads();

    int tid = threadIdx.x;
    int pid = blockIdx.x * BLK + tid;   // pair id
    int i0 = pid * 2;
    if (i0 >= B) return;
    bool haveB = (i0 + 1 < B);

    const float4* xp = reinterpret_cast<const float4*>(x) + (u64)i0 * 2;
    float4 xa0 = xp[0], xb0 = xp[1];
    float4 xa1 = haveB ? xp[2] : xa0;
    float4 xb1 = haveB ? xp[3] : xb0;

    const u64 NL2E = pk2(-L2E, -L2E);

    // sample-packed input components
    u64 X[8];
    X[0] = pk2(xa0.x, xa1.x); X[1] = pk2(xa0.y, xa1.y);
    X[2] = pk2(xa0.z, xa1.z); X[3] = pk2(xa0.w, xa1.w);
    X[4] = pk2(xb0.x, xb1.x); X[5] = pk2(xb0.y, xb1.y);
    X[6] = pk2(xb0.z, xb1.z); X[7] = pk2(xb0.w, xb1.w);

    u64 x2p = mul2_(X[0], X[0]);
#pragma unroll
    for (int c = 1; c < 8; c++) x2p = fma2_(X[c], X[c], x2p);
    u64 nx2L = mul2_(x2p, NL2E);   // -L2E * |x|^2 (packed)

    // RBF: exp2( L2E*(2 x.p - |x|^2 - |p|^2) ); all scales pre-folded
    u64 sP[10];
#pragma unroll
    for (int j = 0; j < 10; j++) {
        const u64* pd = reinterpret_cast<const u64*>(&sm[OFF_PDS + j * 16]);
        u64 dp = mul2_(X[0], pd[0]);
#pragma unroll
        for (int c = 1; c < 8; c++) dp = fma2_(X[c], pd[c], dp);
        u64 pre = *reinterpret_cast<const u64*>(&sm[OFF_PPL + 2 * j]);
        u64 arg = add2_(dp, add2_(nx2L, pre));
        float a0, a1; upk2(arg, a0, a1);
        sP[j] = pk2(ex2_a(a0), ex2_a(a1));
    }

    u64 nP[10], nbA[10], nbB[10];
    u64 accA[5], accB[5];

#pragma unroll
    for (int l = 0; l < 2; l++) {
        const float* A  = &sm[OFF_A  + l * 120];
        const float* aB = &sm[OFF_AB + l * 12];
        const float* W1 = &sm[OFF_W1 + l * 640];
        const float* b1 = &sm[OFF_B1 + l * 64];
        const float* W2 = &sm[OFF_W2 + l * 768];
        const float* b2 = &sm[OFF_B2 + l * 12];

        // ---- attention block (collapsed to folded 10x10 matvec) ----
        ln10p(sP, nP);
        // stash residual: sP dead until the residual add below
#pragma unroll
        for (int p = 0; p < 5; p++) { sc[p][tid] = make_ulonglong2(sP[2 * p], sP[2 * p + 1]); }
#pragma unroll
        for (int i = 0; i < 10; i++) {
            float lo, hi; upk2(nP[i], lo, hi);
            nbA[i] = pk2(lo, lo); nbB[i] = pk2(hi, hi);
        }
#pragma unroll
        for (int p = 0; p < 5; p++) {
            u64 b = *reinterpret_cast<const u64*>(&aB[2 * p]);
            accA[p] = b; accB[p] = b;
        }
#pragma unroll
        for (int i = 0; i < 10; i++) {
            const ulonglong2* ar = reinterpret_cast<const ulonglong2*>(&A[i * 12]);
            ulonglong2 a01 = ar[0];
            ulonglong2 a23 = ar[1];
            u64 a4 = *reinterpret_cast<const u64*>(&A[i * 12 + 8]);
            accA[0] = fma2_(nbA[i], a01.x, accA[0]);  accB[0] = fma2_(nbB[i], a01.x, accB[0]);
            accA[1] = fma2_(nbA[i], a01.y, accA[1]);  accB[1] = fma2_(nbB[i], a01.y, accB[1]);
            accA[2] = fma2_(nbA[i], a23.x, accA[2]);  accB[2] = fma2_(nbB[i], a23.x, accB[2]);
            accA[3] = fma2_(nbA[i], a23.y, accA[3]);  accB[3] = fma2_(nbB[i], a23.y, accB[3]);
            accA[4] = fma2_(nbA[i], a4,    accA[4]);  accB[4] = fma2_(nbB[i], a4,    accB[4]);
        }
#pragma unroll
        for (int p = 0; p < 5; p++) {
            ulonglong2 r = sc[p][tid];                 // reload residual
            float a0, a1, b0, b1v;
            upk2(accA[p], a0, a1); upk2(accB[p], b0, b1v);
            sP[2 * p]     = add2_(r.x, pk2(a0, b0));
            sP[2 * p + 1] = add2_(r.y, pk2(a1, b1v));
        }

        // ---- FFN block ----
        ln10p(sP, nP);
#pragma unroll
        for (int p = 0; p < 5; p++) { sc[p][tid] = make_ulonglong2(sP[2 * p], sP[2 * p + 1]); }
#pragma unroll
        for (int i = 0; i < 10; i++) {
            float lo, hi; upk2(nP[i], lo, hi);
            nbA[i] = pk2(lo, lo); nbB[i] = pk2(hi, hi);
        }
#pragma unroll
        for (int p = 0; p < 5; p++) {
            u64 b = *reinterpret_cast<const u64*>(&b2[2 * p]);
            accA[p] = b; accB[p] = b;
        }
#pragma unroll 1
        for (int f = 0; f < 64; f += 4) {
            u64 bb01 = *reinterpret_cast<const u64*>(&b1[f]);
            u64 bb23 = *reinterpret_cast<const u64*>(&b1[f + 2]);
            u64 tA01 = bb01, tA23 = bb23, tB01 = bb01, tB23 = bb23;
#pragma unroll
            for (int i = 0; i < 10; i++) {
                ulonglong2 w = *reinterpret_cast<const ulonglong2*>(&W1[i * 64 + f]);
                tA01 = fma2_(nbA[i], w.x, tA01);  tB01 = fma2_(nbB[i], w.x, tB01);
                tA23 = fma2_(nbA[i], w.y, tA23);  tB23 = fma2_(nbB[i], w.y, tB23);
            }
            u64 gA01 = gelu2(tA01), gA23 = gelu2(tA23);
            u64 gB01 = gelu2(tB01), gB23 = gelu2(tB23);
            float gA[4], gB[4];
            upk2(gA01, gA[0], gA[1]); upk2(gA23, gA[2], gA[3]);
            upk2(gB01, gB[0], gB[1]); upk2(gB23, gB[2], gB[3]);
#pragma unroll
            for (int fi = 0; fi < 4; fi++) {
                u64 ggA = pk2(gA[fi], gA[fi]);
                u64 ggB = pk2(gB[fi], gB[fi]);
                const ulonglong2* wr = reinterpret_cast<const ulonglong2*>(&W2[(f + fi) * 12]);
                ulonglong2 w01 = wr[0];
                ulonglong2 w23 = wr[1];
                u64 w4 = *reinterpret_cast<const u64*>(&W2[(f + fi) * 12 + 8]);
                accA[0] = fma2_(ggA, w01.x, accA[0]);  accB[0] = fma2_(ggB, w01.x, accB[0]);
                accA[1] = fma2_(ggA, w01.y, accA[1]);  accB[1] = fma2_(ggB, w01.y, accB[1]);
                accA[2] = fma2_(ggA, w23.x, accA[2]);  accB[2] = fma2_(ggB, w23.x, accB[2]);
                accA[3] = fma2_(ggA, w23.y, accA[3]);  accB[3] = fma2_(ggB, w23.y, accB[3]);
                accA[4] = fma2_(ggA, w4,    accA[4]);  accB[4] = fma2_(ggB, w4,    accB[4]);
            }
        }
#pragma unroll
        for (int p = 0; p < 5; p++) {
            ulonglong2 r = sc[p][tid];                 // reload residual
            float a0, a1, b0, b1v;
            upk2(accA[p], a0, a1); upk2(accB[p], b0, b1v);
            sP[2 * p]     = add2_(r.x, pk2(a0, b0));
            sP[2 * p + 1] = add2_(r.y, pk2(a1, b1v));
        }
    }

    // classifier: lp accumulates -L2E*logit; sigma = 1/(1+exp2(lp))
    float bcn = sm[OFF_BCN];
    u64 lp = pk2(bcn, bcn);
#pragma unroll
    for (int j = 0; j < 10; j++) {
        u64 wc = *reinterpret_cast<const u64*>(&sm[OFF_WCN + 2 * j]);
        lp = fma2_(sP[j], wc, lp);
    }
    float lA, lB; upk2(lp, lA, lB);
    float oA = 1.0f / (1.0f + ex2_a(lA));
    float oB = 1.0f / (1.0f + ex2_a(lB));
    if (haveB) {
        *reinterpret_cast<float2*>(out + i0) = make_float2(oA, oB);
    } else {
        out[i0] = oA;
    }
}

// ---------------- launch ----------------
extern "C" void kernel_launch(void* const* d_in, const int* in_sizes, int n_in,
                              void* d_out, int out_size)
{
    const float* x = (const float*)d_in[0];
    int B = in_sizes[0] / 8;

    // input order: x, prototypes, Wq, bq, Wk, bk, Wv, bv, Wo, bo,
    //              ln1_g, ln1_b, ln2_g, ln2_b, W1, b1, W2, b2, Wc, bc
    fold_kernel<<<1, 256>>>(
        (const float*)d_in[1],                           // prototypes
        (const float*)d_in[6],  (const float*)d_in[7],   // Wv, bv
        (const float*)d_in[8],  (const float*)d_in[9],   // Wo, bo
        (const float*)d_in[10], (const float*)d_in[11],  // ln1_g, ln1_b
        (const float*)d_in[12], (const float*)d_in[13],  // ln2_g, ln2_b
        (const float*)d_in[14], (const float*)d_in[15],  // W1, b1
        (const float*)d_in[16], (const float*)d_in[17],  // W2, b2
        (const float*)d_in[18], (const float*)d_in[19]); // Wc, bc

    int pairs = (B + 1) / 2;
    fwd_kernel<<<(pairs + BLK - 1) / BLK, BLK>>>(x, (float*)d_out, B);
}